// round 11
// baseline (speedup 1.0000x reference)
#include <cuda_runtime.h>
#include <cuda_fp16.h>
#include <cstdint>

#define N_ROWS 16384
#define DIMS   128          // bytes per row in fp8
#define SROW   192          // padded smem row stride (bytes); conflict-free LDS.128 frag gathers
#define SEGS   16
#define TPS    (128 / SEGS) // tiles per CTA (bx per segment)

#define BUFSZ   24576       // 128 * 192
#define SM_LAB  73728       // 3 label buffers, 256B each
#define SM_RED  74496       // 8 floats
#define SM_TOT  74560

// exp(-sim/0.5) = 2^(sim * -2*log2(e)); fold scale into B at quantize time.
#define BSCALE (-2.8853900817779268f)

#define CP16(dst_u32, src_ptr) \
    asm volatile("cp.async.cg.shared.global [%0], [%1], 16;" :: "r"(dst_u32), "l"(src_ptr))

// Scratch (allocation-free rule: device globals). Rows are chunk-permuted fp8.
__device__ unsigned char g_A[N_ROWS * DIMS];
__device__ unsigned char g_B[N_ROWS * DIMS];
__device__ __half g_labh[N_ROWS];
__device__ int    g_lab64_flag;
__device__ double g_acc;

// ---------------------------------------------------------------------------
// Kernel 1: L2-normalize rows, convert to e4m3, store chunk-permuted.
// B rows additionally scaled by BSCALE (folds temperature + log2e into GEMM).
// ---------------------------------------------------------------------------
__global__ void normalize_kernel(const float* __restrict__ a,
                                 const float* __restrict__ b) {
    int w    = (blockIdx.x * blockDim.x + threadIdx.x) >> 5;
    int lane = threadIdx.x & 31;
    if (w >= 2 * N_ROWS) return;
    const float* src;
    unsigned char* dst;
    float extra;
    if (w < N_ROWS) { src = a + (size_t)w * 128; dst = g_A + (size_t)w * DIMS; extra = 1.f; }
    else { src = b + (size_t)(w - N_ROWS) * 128; dst = g_B + (size_t)(w - N_ROWS) * DIMS; extra = BSCALE; }

    float4 v = ((const float4*)src)[lane];
    float ss = v.x * v.x + v.y * v.y + v.z * v.z + v.w * v.w;
#pragma unroll
    for (int o = 16; o; o >>= 1) ss += __shfl_xor_sync(0xffffffffu, ss, o);
    float inv = rsqrtf(fmaxf(ss, 1e-24f)) * extra;
    float x0 = v.x * inv, x1 = v.y * inv, x2 = v.z * inv, x3 = v.w * inv;

    unsigned short p01, p23;  // cvt packs: low byte <- second operand
    asm("cvt.rn.satfinite.e4m3x2.f32 %0, %1, %2;" : "=h"(p01) : "f"(x1), "f"(x0));
    asm("cvt.rn.satfinite.e4m3x2.f32 %0, %1, %2;" : "=h"(p23) : "f"(x3), "f"(x2));
    uint32_t word = (uint32_t)p01 | ((uint32_t)p23 << 16);

    int wpos = (4 * (lane >> 4) + (lane & 3)) * 4 + ((lane >> 2) & 3);
    ((uint32_t*)dst)[wpos] = word;
}

// ---------------------------------------------------------------------------
// Kernel 2a/2b: label dtype detection (int64 vs int32) + conversion to half
// ---------------------------------------------------------------------------
__global__ void label_detect_kernel(const long long* __restrict__ lab) {
    int i = blockIdx.x * blockDim.x + threadIdx.x;
    if (i == 0) { g_lab64_flag = 1; g_acc = 0.0; }
    __threadfence();
    if (i < 8192) {
        long long v = lab[i];
        if (v < 0 || v >= 1000000) atomicExch(&g_lab64_flag, 0);
    }
}
__global__ void label_convert_kernel(const void* __restrict__ lab) {
    int i = blockIdx.x * blockDim.x + threadIdx.x;
    if (i < N_ROWS) {
        int l;
        if (g_lab64_flag) l = (int)((const long long*)lab)[i];
        else              l = ((const int*)lab)[i];
        g_labh[i] = __int2half_rn(l);
    }
}

// ---------------------------------------------------------------------------
// Prefetch one 128x128 fp8 B tile (+its labels) into shared buffer `buf`.
// ---------------------------------------------------------------------------
__device__ __forceinline__ void prefetch_tile(uint32_t sb, int tid, int bx, int buf) {
    const char* gB = (const char*)g_B + (size_t)(bx * 128) * DIMS;
    const uint32_t dst = sb + buf * BUFSZ;
#pragma unroll
    for (int q = 0; q < 4; q++) {
        int idx = q * 256 + tid;
        int r = idx >> 3, c = idx & 7;
        CP16(dst + r * SROW + c * 16, gB + idx * 16);
    }
    if (tid < 16)
        CP16(sb + SM_LAB + buf * 256 + tid * 16,
             (const char*)(g_labh + bx * 128) + tid * 16);
    asm volatile("cp.async.commit_group;" ::: "memory");
}

// ---------------------------------------------------------------------------
// Kernel 3: row-persistent fused fp8 GEMM (f16 acc) + exp2/mask/sum.
// Triple-buffered cp.async pipeline with ONE __syncthreads per tile (3 bufs +
// 1 barrier/iter bounds warp skew to 1 iteration, so buffer reuse is safe).
// Tile loop fully unrolled (TPS=8): epilogue of tile i schedules into the
// MMA stream of tile i+1. Body identical to the 205us round-10 kernel.
// ---------------------------------------------------------------------------
__global__ void __launch_bounds__(256, 2) gemm_loss_kernel() {
    extern __shared__ char sm[];
    uint32_t sb = (uint32_t)__cvta_generic_to_shared(sm);
    const int tid  = threadIdx.x;
    const int wid  = tid >> 5;
    const int lane = tid & 31;
    const int wm   = wid >> 1;          // 0..3: 32-row band
    const int wn   = wid & 1;           // 0..1: 64-col band
    const int grp  = lane >> 2;         // 0..7
    const int tig  = lane & 3;          // 0..3

    const int by  = blockIdx.x & 127;
    const int seg = blockIdx.x >> 7;
    const int bx0 = seg * TPS;

    // ---- cache A fragments for this thread's rows, full K=128 (32 regs) ----
    uint4 Af[2][4];                      // [t][rh]; rows grp + 8*rh in 32-row band
#pragma unroll
    for (int rh = 0; rh < 4; rh++)
#pragma unroll
        for (int t = 0; t < 2; t++)
            Af[t][rh] = *(const uint4*)(g_A +
                (size_t)(by * 128 + wm * 32 + grp + 8 * rh) * DIMS + t * 64 + tig * 16);

    const int r0 = wm * 32 + grp;
    __half2 la2[4];
#pragma unroll
    for (int j = 0; j < 4; j++) la2[j] = __half2half2(g_labh[by * 128 + r0 + 8 * j]);

    // ---- prime the pipeline: tiles 0 and 1 ----
    prefetch_tile(sb, tid, bx0 + 0, 0);
    prefetch_tile(sb, tid, bx0 + 1, 1);

    float local = 0.f;
#pragma unroll
    for (int i = 0; i < TPS; i++) {
        if (i + 1 < TPS) { asm volatile("cp.async.wait_group 1;" ::: "memory"); }
        else             { asm volatile("cp.async.wait_group 0;" ::: "memory"); }
        __syncthreads();                 // tile i ready everywhere; iter i-1 reads done
        if (i + 2 < TPS)
            prefetch_tile(sb, tid, bx0 + i + 2, (i + 2) % 3);

        const int buf = i % 3;
        const char*   smB  = sm + buf * BUFSZ;
        const __half* labB = (const __half*)(sm + SM_LAB + buf * 256);

        // f16 accumulators: acc[mi][ni][0] = half2(c0,c1) row r0+16mi;
        //                   acc[mi][ni][1] = half2(c2,c3) row r0+16mi+8
        uint32_t acc[2][8][2];
#pragma unroll
        for (int mi = 0; mi < 2; mi++)
#pragma unroll
            for (int ni = 0; ni < 8; ni++) { acc[mi][ni][0] = 0u; acc[mi][ni][1] = 0u; }

        const char* bP = smB + (wn * 64 + grp) * SROW + tig * 16;
#pragma unroll
        for (int t = 0; t < 2; t++) {
            uint4 Bf[8];
#pragma unroll
            for (int ni = 0; ni < 8; ni++)
                Bf[ni] = *(const uint4*)(bP + ni * 8 * SROW + t * 64);
#pragma unroll
            for (int s = 0; s < 2; s++) {
#pragma unroll
                for (int ni = 0; ni < 8; ni++) {
                    const uint32_t* B_w = (const uint32_t*)&Bf[ni];
#pragma unroll
                    for (int mi = 0; mi < 2; mi++) {
                        const uint32_t* A0 = (const uint32_t*)&Af[t][2 * mi];
                        const uint32_t* A1 = (const uint32_t*)&Af[t][2 * mi + 1];
                        asm volatile(
                            "mma.sync.aligned.m16n8k32.row.col.f16.e4m3.e4m3.f16 "
                            "{%0,%1}, {%2,%3,%4,%5}, {%6,%7}, {%0,%1};"
                            : "+r"(acc[mi][ni][0]), "+r"(acc[mi][ni][1])
                            : "r"(A0[2 * s]), "r"(A1[2 * s]),
                              "r"(A0[2 * s + 1]), "r"(A1[2 * s + 1]),
                              "r"(B_w[2 * s]), "r"(B_w[2 * s + 1]));
                    }
                }
            }
        }

        // ---- epilogue: sum 2^acc over label-differing pairs (all-f16x2) ----
        const int c0 = wn * 64 + 2 * tig;
        __half2 tsum = __float2half2_rn(0.f);
#pragma unroll
        for (int mi = 0; mi < 2; mi++) {
#pragma unroll
            for (int ni = 0; ni < 8; ni++) {
                __half2 lb2 = *(const __half2*)&labB[c0 + ni * 8];
                __half2 e0 = h2exp2(*(const __half2*)&acc[mi][ni][0]);
                __half2 e1 = h2exp2(*(const __half2*)&acc[mi][ni][1]);
                __half2 m0 = __hne2(la2[2 * mi], lb2);
                __half2 m1 = __hne2(la2[2 * mi + 1], lb2);
                tsum = __hfma2(e0, m0, tsum);
                tsum = __hfma2(e1, m1, tsum);
            }
        }
        local += __low2float(tsum) + __high2float(tsum);
        // no trailing barrier: next iteration's barrier protects buffer reuse
    }

    // ---- block reduction + single atomic ----
#pragma unroll
    for (int o = 16; o; o >>= 1) local += __shfl_xor_sync(0xffffffffu, local, o);
    float* red = (float*)(sm + SM_RED);
    if (lane == 0) red[wid] = local;
    __syncthreads();
    if (tid == 0) {
        float s = 0.f;
#pragma unroll
        for (int w = 0; w < 8; w++) s += red[w];
        atomicAdd(&g_acc, (double)s);
    }
}

// ---------------------------------------------------------------------------
// Kernel 4: finalize scalar
// ---------------------------------------------------------------------------
__global__ void finalize_kernel(float* __restrict__ out) {
    out[0] = (float)(g_acc / ((double)N_ROWS * (double)(N_ROWS - 1)));
}

extern "C" void kernel_launch(void* const* d_in, const int* in_sizes, int n_in,
                              void* d_out, int out_size) {
    const float* a   = (const float*)d_in[0];
    const float* b   = (const float*)d_in[1];
    const void*  lab = d_in[2];
    float* out = (float*)d_out;

    normalize_kernel<<<(2 * N_ROWS * 32) / 256, 256>>>(a, b);
    label_detect_kernel<<<(8192 + 255) / 256, 256>>>((const long long*)lab);
    label_convert_kernel<<<(N_ROWS + 255) / 256, 256>>>(lab);

    cudaFuncSetAttribute(gemm_loss_kernel,
                         cudaFuncAttributeMaxDynamicSharedMemorySize, SM_TOT);
    gemm_loss_kernel<<<128 * SEGS, 256, SM_TOT>>>();

    finalize_kernel<<<1, 1>>>(out);
}